// round 16
// baseline (speedup 1.0000x reference)
#include <cuda_runtime.h>
#include <cstdint>

#define N_TYPES 95

// Precomputed constants (device globals: no allocation allowed)
__device__ float    g_PT[N_TYPES * 256];            // PT1 (with b_dense) | PT2
__device__ unsigned g_W3F[8192];                    // W3 bf16x2, m16n8k16 B-fragment order
__device__ float    g_PTS[N_TYPES * N_TYPES * 128]; // PT1[zs]+PT2[zd] pair table (4.6MB)

// silu via tanh: x*sigmoid(x) = h + h*tanh(h), h = x/2.  1 MUFU instead of 2.
__device__ __forceinline__ float silu_f(float x) {
    float h = 0.5f * x, t;
    asm("tanh.approx.f32 %0, %1;" : "=f"(t) : "f"(h));
    return fmaf(h, t, h);
}
__device__ __forceinline__ unsigned pack_bf16(float hi, float lo) {
    unsigned r; asm("cvt.rn.bf16x2.f32 %0, %1, %2;" : "=r"(r) : "f"(hi), "f"(lo)); return r;
}
// bf16 mma m16n8k16: A={a0..a3} (bf16x2 each), B={b0,b1}, C f32
__device__ __forceinline__ void mma_bf16(float c[4],
                                         unsigned a0, unsigned a1, unsigned a2, unsigned a3,
                                         unsigned b0, unsigned b1) {
    asm volatile(
        "mma.sync.aligned.m16n8k16.row.col.f32.bf16.bf16.f32 "
        "{%0,%1,%2,%3}, {%4,%5,%6,%7}, {%8,%9}, {%0,%1,%2,%3};"
        : "+f"(c[0]), "+f"(c[1]), "+f"(c[2]), "+f"(c[3])
        : "r"(a0), "r"(a1), "r"(a2), "r"(a3), "r"(b0), "r"(b1));
}
__device__ __forceinline__ void cp_async16(uint32_t saddr, const void* gptr) {
    asm volatile("cp.async.ca.shared.global [%0], [%1], 16;" :: "r"(saddr), "l"(gptr) : "memory");
}
#define CP_COMMIT()  asm volatile("cp.async.commit_group;" ::: "memory")
#define CP_WAIT(n)   asm volatile("cp.async.wait_group %0;" :: "n"(n) : "memory")

// packed f32x2 (FFMA2) — only reachable via PTX fma.rn.f32x2
typedef unsigned long long u64f2;
__device__ __forceinline__ u64f2 pack_f32x2(float lo, float hi) {
    u64f2 r; asm("mov.b64 %0, {%1, %2};" : "=l"(r) : "f"(lo), "f"(hi)); return r;
}
__device__ __forceinline__ float2 unpack_f32x2(u64f2 v) {
    float2 f; asm("mov.b64 {%0, %1}, %2;" : "=f"(f.x), "=f"(f.y) : "l"(v)); return f;
}
__device__ __forceinline__ void fma_f32x2(u64f2& d, u64f2 a, u64f2 b) {
    asm("fma.rn.f32x2 %0, %1, %2, %0;" : "+l"(d) : "l"(a), "l"(b));
}

// ---------------------------------------------------------------------------
// Precompute 1: PT[95][256] + W3 bf16 fragments (layout as R10+).
// ---------------------------------------------------------------------------
__global__ void precompute_kernel(const float* __restrict__ emb,
                                  const float* __restrict__ Wd,
                                  const float* __restrict__ bd) {
    int b = blockIdx.x, t = threadIdx.x;
    if (b < N_TYPES) {
        __shared__ float er[128];
        if (t < 128) er[t] = emb[b * 128 + t];
        __syncthreads();
        int i = t & 127, half = t >> 7;
        const float4* w4 = (const float4*)(Wd + (size_t)i * 384 + half * 128);
        float acc = (half == 0) ? bd[i] : 0.0f;   // fold b_dense into PT1
        #pragma unroll
        for (int k4 = 0; k4 < 32; k4++) {
            float4 w = w4[k4];
            acc += er[k4*4+0]*w.x + er[k4*4+1]*w.y + er[k4*4+2]*w.z + er[k4*4+3]*w.w;
        }
        g_PT[b * 256 + half * 128 + i] = acc;
    } else {
        int idx  = (b - N_TYPES) * 256 + t;   // 0..8191
        int s    = idx & 3;
        int lane = (idx >> 2) & 31;
        int p    = (idx >> 7) & 7;
        int kc   = (idx >> 10) & 7;
        int ntg  = 2 * p + (s >> 1);
        int bsel = s & 1;
        int g    = lane >> 2, q = lane & 3;
        int col  = ntg * 8 + g;
        int k0   = kc * 16 + 2 * q + bsel * 8;
        const float* wrow = Wd + (size_t)col * 384 + 256;
        g_W3F[idx] = pack_bf16(wrow[k0 + 1], wrow[k0]);
    }
}

// Precompute 2: pair-sum table, grid-stride float4
__global__ void ptsum_kernel() {
    int stride = gridDim.x * blockDim.x;
    for (int i = blockIdx.x * blockDim.x + threadIdx.x;
         i < N_TYPES * N_TYPES * 32; i += stride) {
        int pair = i >> 5, c4 = (i & 31) * 4;
        int zs = pair / N_TYPES, zd = pair - zs * N_TYPES;
        float4 a = *(const float4*)(g_PT + zs * 256 + c4);
        float4 b = *(const float4*)(g_PT + zd * 256 + 128 + c4);
        float4 v = make_float4(a.x + b.x, a.y + b.y, a.z + b.z, a.w + b.w);
        *(float4*)(g_PTS + (size_t)pair * 128 + c4) = v;
    }
}

// ---------------------------------------------------------------------------
// Main fused kernel: 2 CTAs/SM x 256 threads, 64-edge tiles, cross-tile
// software pipeline, ONE barrier per tile. B fragments register-resident,
// Wr fragment-packed, streaming inputs via cp.async 3-slot ring.
// NEW vs R15: phase A uses packed fma.rn.f32x2 (FFMA2) — half the FMA issue.
// ---------------------------------------------------------------------------
#define HF_WORDS  4096              // one H buffer: 64 rows x 128 k bf16 (16 KB)
#define WRF_WORDS 3072              // WrF: 32 (kc,q) combos x 6 j x float4
#define BRF_WORDS 128               // brF: 32 combos x float4
#define RB_WORDS  576               // per slot: rbf 384 | dvec 64 | src 64 | dst 64
#define SMEM_WORDS (2*HF_WORDS + WRF_WORDS + BRF_WORDS + 3*RB_WORDS)
#define SMEM_BYTES (SMEM_WORDS * 4) // 52,864 B (2 CTAs fit)

// Fill one ring slot with tile inputs. Fast path: 144 x cp.async(16B).
__device__ __forceinline__ void fill_slot(
    unsigned* slot, uint32_t slot_u32, int base, int tid, int E,
    const float* __restrict__ rbf, const float* __restrict__ dvec,
    const int* __restrict__ src, const int* __restrict__ dst)
{
    if (base + 64 <= E) {
        if (tid < 144) {
            const char* gsrc;
            if (tid < 96)       gsrc = (const char*)(rbf + (size_t)base * 6) + tid * 16;
            else if (tid < 112) gsrc = (const char*)(dvec + base) + (tid - 96) * 16;
            else if (tid < 128) gsrc = (const char*)(src + base) + (tid - 112) * 16;
            else                gsrc = (const char*)(dst + base) + (tid - 128) * 16;
            cp_async16(slot_u32 + tid * 16, gsrc);
        }
    } else {
        // partial tail tile: guarded synchronous fills (visible after next barrier)
        for (int i = tid; i < RB_WORDS; i += 256) {
            if (i < 384) {
                int e = base + i / 6;
                ((float*)slot)[i] = (e < E) ? rbf[(size_t)e * 6 + i % 6] : 0.0f;
            } else if (i < 448) {
                int e = base + (i - 384);
                ((float*)slot)[i] = (e < E) ? dvec[e] : 1.0f;
            } else if (i < 512) {
                int e = base + (i - 448);
                ((int*)slot)[i] = (e < E) ? src[e] : 0;
            } else {
                int e = base + (i - 512);
                ((int*)slot)[i] = (e < E) ? dst[e] : 0;
            }
        }
    }
}

// Phase A: H = silu(rbf @ Wr^T + b) for this warp's 16-row group and 4-chunk
// range, written in mma A-fragment layout. Packed FFMA2 inner loop.
__device__ __forceinline__ void phase_a(
    uint4* HFdst, const float* slot, int rA0, int rgA, int kcA,
    int lane, int q, const u64f2* WrF2, const u64f2* brF2)
{
    const float2* rrow = (const float2*)slot;
    u64f2 rbA2[6], rbB2[6];
    #pragma unroll
    for (int j2 = 0; j2 < 3; j2++) {
        float2 a = rrow[rA0 * 3 + j2];
        float2 b = rrow[(rA0 + 8) * 3 + j2];
        rbA2[2*j2]   = pack_f32x2(a.x, a.x);
        rbA2[2*j2+1] = pack_f32x2(a.y, a.y);
        rbB2[2*j2]   = pack_f32x2(b.x, b.x);
        rbB2[2*j2+1] = pack_f32x2(b.y, b.y);
    }
    #pragma unroll
    for (int kk = 0; kk < 4; kk++) {
        int kc = kcA + kk;
        int eb = (kc * 4 + q);
        u64f2 aA01 = brF2[eb * 2], aA23 = brF2[eb * 2 + 1];
        u64f2 aB01 = aA01, aB23 = aA23;
        #pragma unroll
        for (int j = 0; j < 6; j++) {
            u64f2 wxy = WrF2[(eb * 6 + j) * 2];
            u64f2 wzw = WrF2[(eb * 6 + j) * 2 + 1];
            fma_f32x2(aA01, rbA2[j], wxy);
            fma_f32x2(aA23, rbA2[j], wzw);
            fma_f32x2(aB01, rbB2[j], wxy);
            fma_f32x2(aB23, rbB2[j], wzw);
        }
        float2 A01 = unpack_f32x2(aA01), A23 = unpack_f32x2(aA23);
        float2 B01 = unpack_f32x2(aB01), B23 = unpack_f32x2(aB23);
        uint4 v;
        v.x = pack_bf16(silu_f(A01.y), silu_f(A01.x));   // row g,   k c0..c0+1
        v.y = pack_bf16(silu_f(B01.y), silu_f(B01.x));   // row g+8, k c0..c0+1
        v.z = pack_bf16(silu_f(A23.y), silu_f(A23.x));   // row g,   k c0+8..c0+9
        v.w = pack_bf16(silu_f(B23.y), silu_f(B23.x));   // row g+8, k c0+8..c0+9
        HFdst[(rgA * 8 + kc) * 32 + lane] = v;
    }
}

__global__ void __launch_bounds__(256, 2) main_kernel(
    const int* __restrict__ Z, const int* __restrict__ src, const int* __restrict__ dst,
    const float* __restrict__ rbf, const float* __restrict__ dvec,
    const float* __restrict__ Wr, const float* __restrict__ brbf,
    float* __restrict__ out, int E, int nTiles)
{
    extern __shared__ unsigned sm[];
    uint4*    HF0   = (uint4*)sm;
    uint4*    HF1   = HF0 + (HF_WORDS / 4);
    float*    WrF_s = (float*)(sm + 2 * HF_WORDS);
    float*    brF_s = WrF_s + WRF_WORDS;
    unsigned* RB    = sm + 2 * HF_WORDS + WRF_WORDS + BRF_WORDS;   // 3 slots

    int tid = threadIdx.x;
    // Wr fragment pack: WrF[(kc*4+q)*6 + j] = {Wr[c0][j],Wr[c0+1][j],Wr[c0+8][j],Wr[c0+9][j]}
    for (int i = tid; i < WRF_WORDS; i += 256) {
        int entry = i >> 2, comp = i & 3;
        int kc = entry / 24, rem = entry - kc * 24;
        int qq = rem / 6, j = rem - qq * 6;
        int col = kc * 16 + 2 * qq + (comp & 1) + ((comp >> 1) * 8);
        WrF_s[i] = __ldg(Wr + col * 6 + j);
    }
    for (int i = tid; i < BRF_WORDS; i += 256) {
        int entry = i >> 2, comp = i & 3;
        int kc = entry >> 2, qq = entry & 3;
        int col = kc * 16 + 2 * qq + (comp & 1) + ((comp >> 1) * 8);
        brF_s[i] = __ldg(brbf + col);
    }

    int lane = tid & 31, w = tid >> 5;
    int g = lane >> 2, q = lane & 3;
    int rgA = w & 3, kcA = (w >> 2) * 4;  // phase A: row-group (0..3), chunk range
    int rA0 = rgA * 16 + g;
    int mq = w >> 2, h = w & 3;           // phase B: 32-row group, 32-col quarter
    size_t envBase = (size_t)E * 128;
    const float PIf = 3.14159265358979323846f;
    const u64f2* WrF2 = (const u64f2*)WrF_s;
    const u64f2* brF2 = (const u64f2*)brF_s;
    uint32_t RB_u32 = (uint32_t)__cvta_generic_to_shared(RB);

    // W3 B-fragments: register-resident for this warp's column quarter
    uint4 BR0[8], BR1[8];
    {
        const uint4* GW = (const uint4*)g_W3F;
        #pragma unroll
        for (int kc = 0; kc < 8; kc++) {
            BR0[kc] = __ldg(GW + (kc * 8 + 2 * h)     * 32 + lane);
            BR1[kc] = __ldg(GW + (kc * 8 + 2 * h + 1) * 32 + lane);
        }
    }

    int t = blockIdx.x;
    if (t >= nTiles) return;
    int grid = gridDim.x;

    // ---- prologue: stage T0, T1; then A(T0) into HF0 ----
    fill_slot(RB, RB_u32, t * 64, tid, E, rbf, dvec, src, dst);
    CP_COMMIT();
    if (t + grid < nTiles)
        fill_slot(RB + RB_WORDS, RB_u32 + RB_WORDS * 4, (t + grid) * 64, tid, E, rbf, dvec, src, dst);
    CP_COMMIT();
    CP_WAIT(1);          // slot 0 (T0) complete
    __syncthreads();     // all fills + WrF/brF visible

    phase_a(HF0, (const float*)RB, rA0, rgA, kcA, lane, q, WrF2, brF2);

    int p = 0, sc = 0;

    // ---- pipelined main loop: one barrier per tile ----
    while (t < nTiles) {
        CP_WAIT(0);                            // next tile's slot complete (own)
        __syncthreads();                       // HF[p] + all fills visible
        int base = t * 64;
        int tn = t + grid;
        uint4* HFr = p ? HF1 : HF0;            // B reads
        uint4* HFw = p ? HF0 : HF1;            // A writes
        unsigned* SC = RB + sc * RB_WORDS;             // current tile inputs
        int sn = sc + 1; if (sn >= 3) sn = 0;
        unsigned* SN = RB + sn * RB_WORDS;             // next tile inputs
        int sf = sc + 2; if (sf >= 3) sf -= 3;         // (sc+2) mod 3

        // stage tile t + 2*grid (2 iterations of cover)
        int tf = tn + grid;
        if (tf < nTiles)
            fill_slot(RB + sf * RB_WORDS, RB_u32 + (unsigned)sf * RB_WORDS * 4,
                      tf * 64, tid, E, rbf, dvec, src, dst);
        CP_COMMIT();

        const float* dv_s  = (const float*)SC + 384;
        const int*   src_s = (const int*)SC + 448;
        const int*   dst_s = (const int*)SC + 512;

        // epilogue z-chain (src/dst from SMEM; Z + PTS are L2-hot)
        int r0 = (2 * mq) * 16 + g;            // mt=0 base row
        int r1 = r0 + 16;                      // mt=1 base row
        int e00 = base + r0, e01 = e00 + 8;
        int e10 = base + r1, e11 = e10 + 8;
        int s00 = src_s[r0],     d00 = dst_s[r0];
        int s01 = src_s[r0 + 8], d01 = dst_s[r0 + 8];
        int s10 = src_s[r1],     d10 = dst_s[r1];
        int s11 = src_s[r1 + 8], d11 = dst_s[r1 + 8];

        // bessel / envelope branch for tile t: 128 threads, 3 sins each
        if (tid < 128) {
            int e = base + (tid >> 1);
            if (e < E) {
                int half3 = (tid & 1) * 3;
                float x = dv_s[tid >> 1] * 0.2f;
                float inv = 1.0f / x;
                float x2 = x*x, x4 = x2*x2, x5 = x4*x, x6 = x5*x, x7 = x6*x;
                float env = inv - 28.0f*x5 + 48.0f*x6 - 21.0f*x7;   // p = 6
                float s = env * inv;
                float* oo = out + envBase + (size_t)e * 6 + half3;
                #pragma unroll
                for (int n = 1; n <= 3; n++)
                    oo[n - 1] = s * __sinf(((float)(n + half3) * PIf) * x);
            }
        }

        const float* P00 = g_PTS + ((size_t)__ldg(Z + s00) * N_TYPES + __ldg(Z + d00)) * 128;
        const float* P01 = g_PTS + ((size_t)__ldg(Z + s01) * N_TYPES + __ldg(Z + d01)) * 128;
        const float* P10 = g_PTS + ((size_t)__ldg(Z + s10) * N_TYPES + __ldg(Z + d10)) * 128;
        const float* P11 = g_PTS + ((size_t)__ldg(Z + s11) * N_TYPES + __ldg(Z + d11)) * 128;

        // ---- phase A(tn) -> HFw (rbf from SMEM slot sn, packed FFMA2) ----
        if (tn < nTiles)
            phase_a(HFw, (const float*)SN, rA0, rgA, kcA, lane, q, WrF2, brF2);

        // ---- MMA loop: A via LDS.128, B from registers ----
        float c[2][4][4];
        #pragma unroll
        for (int mt = 0; mt < 2; mt++)
            #pragma unroll
            for (int nt = 0; nt < 4; nt++)
                { c[mt][nt][0]=0.f; c[mt][nt][1]=0.f; c[mt][nt][2]=0.f; c[mt][nt][3]=0.f; }

        #pragma unroll
        for (int kc = 0; kc < 8; kc++) {
            uint4 A0 = HFr[((2 * mq)     * 8 + kc) * 32 + lane];
            uint4 A1 = HFr[((2 * mq + 1) * 8 + kc) * 32 + lane];
            uint4 B0 = BR0[kc], B1 = BR1[kc];
            mma_bf16(c[0][0], A0.x, A0.y, A0.z, A0.w, B0.x, B0.y);
            mma_bf16(c[0][1], A0.x, A0.y, A0.z, A0.w, B0.z, B0.w);
            mma_bf16(c[0][2], A0.x, A0.y, A0.z, A0.w, B1.x, B1.y);
            mma_bf16(c[0][3], A0.x, A0.y, A0.z, A0.w, B1.z, B1.w);
            mma_bf16(c[1][0], A1.x, A1.y, A1.z, A1.w, B0.x, B0.y);
            mma_bf16(c[1][1], A1.x, A1.y, A1.z, A1.w, B0.z, B0.w);
            mma_bf16(c[1][2], A1.x, A1.y, A1.z, A1.w, B1.x, B1.y);
            mma_bf16(c[1][3], A1.x, A1.y, A1.z, A1.w, B1.z, B1.w);
        }

        // ---- epilogue mt=0 ----
        {
            float* o0 = out + (size_t)e00 * 128;
            float* o1 = out + (size_t)e01 * 128;
            bool st0 = (e00 < E), st1 = (e01 < E);
            #pragma unroll
            for (int nt = 0; nt < 4; nt++) {
                int col = h * 32 + nt * 8 + q * 2;
                float2 pa = __ldg((const float2*)(P00 + col));
                float2 pb = __ldg((const float2*)(P01 + col));
                float2 v0, v1;
                v0.x = silu_f(c[0][nt][0] + pa.x);
                v0.y = silu_f(c[0][nt][1] + pa.y);
                v1.x = silu_f(c[0][nt][2] + pb.x);
                v1.y = silu_f(c[0][nt][3] + pb.y);
                if (st0) *(float2*)(o0 + col) = v0;
                if (st1) *(float2*)(o1 + col) = v1;
            }
        }
        // ---- epilogue mt=1 ----
        {
            float* o0 = out + (size_t)e10 * 128;
            float* o1 = out + (size_t)e11 * 128;
            bool st0 = (e10 < E), st1 = (e11 < E);
            #pragma unroll
            for (int nt = 0; nt < 4; nt++) {
                int col = h * 32 + nt * 8 + q * 2;
                float2 pa = __ldg((const float2*)(P10 + col));
                float2 pb = __ldg((const float2*)(P11 + col));
                float2 v0, v1;
                v0.x = silu_f(c[1][nt][0] + pa.x);
                v0.y = silu_f(c[1][nt][1] + pa.y);
                v1.x = silu_f(c[1][nt][2] + pb.x);
                v1.y = silu_f(c[1][nt][3] + pb.y);
                if (st0) *(float2*)(o0 + col) = v0;
                if (st1) *(float2*)(o1 + col) = v1;
            }
        }

        t = tn; p ^= 1; sc = sn;
    }
}

extern "C" void kernel_launch(void* const* d_in, const int* in_sizes, int n_in,
                              void* d_out, int out_size) {
    const int*   Z    = (const int*)d_in[0];
    const int*   src  = (const int*)d_in[1];
    const int*   dst  = (const int*)d_in[2];
    const float* rbf  = (const float*)d_in[3];
    const float* d    = (const float*)d_in[4];
    const float* emb  = (const float*)d_in[5];
    const float* Wr   = (const float*)d_in[6];
    const float* brbf = (const float*)d_in[7];
    const float* Wd   = (const float*)d_in[8];
    const float* bd   = (const float*)d_in[9];
    int E = in_sizes[1];
    int nTiles = (E + 63) / 64;

    precompute_kernel<<<N_TYPES + 32, 256>>>(emb, Wd, bd);
    ptsum_kernel<<<1184, 256>>>();

    cudaFuncSetAttribute(main_kernel, cudaFuncAttributeMaxDynamicSharedMemorySize, SMEM_BYTES);
    int dev = 0, nsm = 148;
    cudaGetDevice(&dev);
    cudaDeviceGetAttribute(&nsm, cudaDevAttrMultiProcessorCount, dev);

    main_kernel<<<2 * nsm, 256, SMEM_BYTES>>>(Z, src, dst, rbf, d, Wr, brbf,
                                              (float*)d_out, E, nTiles);
}

// round 17
// speedup vs baseline: 1.1829x; 1.1829x over previous
#include <cuda_runtime.h>
#include <cstdint>

#define N_TYPES 95

// Precomputed constants (device globals: no allocation allowed)
__device__ float    g_PT[N_TYPES * 256];            // PT1 (with b_dense) | PT2
__device__ unsigned g_W3F[8192];                    // W3 bf16x2, m16n8k16 B-fragment order (paired-interleaved cols)
__device__ float    g_PTS[N_TYPES * N_TYPES * 128]; // PT1[zs]+PT2[zd] pair table (4.6MB)

// silu via tanh: x*sigmoid(x) = h + h*tanh(h), h = x/2.  1 MUFU instead of 2.
__device__ __forceinline__ float silu_f(float x) {
    float h = 0.5f * x, t;
    asm("tanh.approx.f32 %0, %1;" : "=f"(t) : "f"(h));
    return fmaf(h, t, h);
}
__device__ __forceinline__ unsigned pack_bf16(float hi, float lo) {
    unsigned r; asm("cvt.rn.bf16x2.f32 %0, %1, %2;" : "=r"(r) : "f"(hi), "f"(lo)); return r;
}
// bf16 mma m16n8k16: A={a0..a3} (bf16x2 each), B={b0,b1}, C f32
__device__ __forceinline__ void mma_bf16(float c[4],
                                         unsigned a0, unsigned a1, unsigned a2, unsigned a3,
                                         unsigned b0, unsigned b1) {
    asm volatile(
        "mma.sync.aligned.m16n8k16.row.col.f32.bf16.bf16.f32 "
        "{%0,%1,%2,%3}, {%4,%5,%6,%7}, {%8,%9}, {%0,%1,%2,%3};"
        : "+f"(c[0]), "+f"(c[1]), "+f"(c[2]), "+f"(c[3])
        : "r"(a0), "r"(a1), "r"(a2), "r"(a3), "r"(b0), "r"(b1));
}
__device__ __forceinline__ void cp_async16(uint32_t saddr, const void* gptr) {
    asm volatile("cp.async.ca.shared.global [%0], [%1], 16;" :: "r"(saddr), "l"(gptr) : "memory");
}
#define CP_COMMIT()  asm volatile("cp.async.commit_group;" ::: "memory")
#define CP_WAIT(n)   asm volatile("cp.async.wait_group %0;" :: "n"(n) : "memory")

// packed f32x2 (FFMA2) — only reachable via PTX fma.rn.f32x2
typedef unsigned long long u64f2;
__device__ __forceinline__ u64f2 pack_f32x2(float lo, float hi) {
    u64f2 r; asm("mov.b64 %0, {%1, %2};" : "=l"(r) : "f"(lo), "f"(hi)); return r;
}
__device__ __forceinline__ float2 unpack_f32x2(u64f2 v) {
    float2 f; asm("mov.b64 {%0, %1}, %2;" : "=f"(f.x), "=f"(f.y) : "l"(v)); return f;
}
__device__ __forceinline__ void fma_f32x2(u64f2& d, u64f2 a, u64f2 b) {
    asm("fma.rn.f32x2 %0, %1, %2, %0;" : "+l"(d) : "l"(a), "l"(b));
}

// ---------------------------------------------------------------------------
// Precompute 1: PT[95][256] + W3 bf16 fragments.
// NEW column mapping (pair-interleaved): fragment pair p (0..7) covers logical
// columns [p*16, p*16+16); within the pair, tile t (=s>>1) maps its B-index g
// to logical column (g>>1)*4 + 2t + (g&1). Thread q then owns 4 CONSECUTIVE
// logical columns per pair in D -> float4 epilogue.
// ---------------------------------------------------------------------------
__global__ void precompute_kernel(const float* __restrict__ emb,
                                  const float* __restrict__ Wd,
                                  const float* __restrict__ bd) {
    int b = blockIdx.x, t = threadIdx.x;
    if (b < N_TYPES) {
        __shared__ float er[128];
        if (t < 128) er[t] = emb[b * 128 + t];
        __syncthreads();
        int i = t & 127, half = t >> 7;
        const float4* w4 = (const float4*)(Wd + (size_t)i * 384 + half * 128);
        float acc = (half == 0) ? bd[i] : 0.0f;   // fold b_dense into PT1
        #pragma unroll
        for (int k4 = 0; k4 < 32; k4++) {
            float4 w = w4[k4];
            acc += er[k4*4+0]*w.x + er[k4*4+1]*w.y + er[k4*4+2]*w.z + er[k4*4+3]*w.w;
        }
        g_PT[b * 256 + half * 128 + i] = acc;
    } else {
        int idx  = (b - N_TYPES) * 256 + t;   // 0..8191
        int s    = idx & 3;
        int lane = (idx >> 2) & 31;
        int p    = (idx >> 7) & 7;
        int kc   = (idx >> 10) & 7;
        int t2   = s >> 1;                    // tile within pair
        int bsel = s & 1;
        int g    = lane >> 2, q = lane & 3;
        int col  = p * 16 + ((g >> 1) << 2) + 2 * t2 + (g & 1);  // pair-interleaved
        int k0   = kc * 16 + 2 * q + bsel * 8;
        const float* wrow = Wd + (size_t)col * 384 + 256;
        g_W3F[idx] = pack_bf16(wrow[k0 + 1], wrow[k0]);
    }
}

// Precompute 2: pair-sum table, grid-stride float4
__global__ void ptsum_kernel() {
    int stride = gridDim.x * blockDim.x;
    for (int i = blockIdx.x * blockDim.x + threadIdx.x;
         i < N_TYPES * N_TYPES * 32; i += stride) {
        int pair = i >> 5, c4 = (i & 31) * 4;
        int zs = pair / N_TYPES, zd = pair - zs * N_TYPES;
        float4 a = *(const float4*)(g_PT + zs * 256 + c4);
        float4 b = *(const float4*)(g_PT + zd * 256 + 128 + c4);
        float4 v = make_float4(a.x + b.x, a.y + b.y, a.z + b.z, a.w + b.w);
        *(float4*)(g_PTS + (size_t)pair * 128 + c4) = v;
    }
}

// ---------------------------------------------------------------------------
// Main fused kernel: 2 CTAs/SM x 256 threads, 64-edge tiles, cross-tile
// software pipeline, ONE barrier per tile. B fragments register-resident,
// Wr fragment-packed, streaming inputs via cp.async 3-slot ring, FFMA2 phase A.
// NEW vs R16: float4 epilogue (pair-interleaved columns) + float2 bessel stores.
// ---------------------------------------------------------------------------
#define HF_WORDS  4096              // one H buffer: 64 rows x 128 k bf16 (16 KB)
#define WRF_WORDS 3072              // WrF: 32 (kc,q) combos x 6 j x float4
#define BRF_WORDS 128               // brF: 32 combos x float4
#define RB_WORDS  576               // per slot: rbf 384 | dvec 64 | src 64 | dst 64
#define SMEM_WORDS (2*HF_WORDS + WRF_WORDS + BRF_WORDS + 3*RB_WORDS)
#define SMEM_BYTES (SMEM_WORDS * 4) // 52,864 B (2 CTAs fit)

// Fill one ring slot with tile inputs. Fast path: 144 x cp.async(16B).
__device__ __forceinline__ void fill_slot(
    unsigned* slot, uint32_t slot_u32, int base, int tid, int E,
    const float* __restrict__ rbf, const float* __restrict__ dvec,
    const int* __restrict__ src, const int* __restrict__ dst)
{
    if (base + 64 <= E) {
        if (tid < 144) {
            const char* gsrc;
            if (tid < 96)       gsrc = (const char*)(rbf + (size_t)base * 6) + tid * 16;
            else if (tid < 112) gsrc = (const char*)(dvec + base) + (tid - 96) * 16;
            else if (tid < 128) gsrc = (const char*)(src + base) + (tid - 112) * 16;
            else                gsrc = (const char*)(dst + base) + (tid - 128) * 16;
            cp_async16(slot_u32 + tid * 16, gsrc);
        }
    } else {
        // partial tail tile: guarded synchronous fills (visible after next barrier)
        for (int i = tid; i < RB_WORDS; i += 256) {
            if (i < 384) {
                int e = base + i / 6;
                ((float*)slot)[i] = (e < E) ? rbf[(size_t)e * 6 + i % 6] : 0.0f;
            } else if (i < 448) {
                int e = base + (i - 384);
                ((float*)slot)[i] = (e < E) ? dvec[e] : 1.0f;
            } else if (i < 512) {
                int e = base + (i - 448);
                ((int*)slot)[i] = (e < E) ? src[e] : 0;
            } else {
                int e = base + (i - 512);
                ((int*)slot)[i] = (e < E) ? dst[e] : 0;
            }
        }
    }
}

// Phase A: H = silu(rbf @ Wr^T + b), mma A-fragment layout, packed FFMA2.
__device__ __forceinline__ void phase_a(
    uint4* HFdst, const float* slot, int rA0, int rgA, int kcA,
    int lane, int q, const u64f2* WrF2, const u64f2* brF2)
{
    const float2* rrow = (const float2*)slot;
    u64f2 rbA2[6], rbB2[6];
    #pragma unroll
    for (int j2 = 0; j2 < 3; j2++) {
        float2 a = rrow[rA0 * 3 + j2];
        float2 b = rrow[(rA0 + 8) * 3 + j2];
        rbA2[2*j2]   = pack_f32x2(a.x, a.x);
        rbA2[2*j2+1] = pack_f32x2(a.y, a.y);
        rbB2[2*j2]   = pack_f32x2(b.x, b.x);
        rbB2[2*j2+1] = pack_f32x2(b.y, b.y);
    }
    #pragma unroll
    for (int kk = 0; kk < 4; kk++) {
        int kc = kcA + kk;
        int eb = (kc * 4 + q);
        u64f2 aA01 = brF2[eb * 2], aA23 = brF2[eb * 2 + 1];
        u64f2 aB01 = aA01, aB23 = aA23;
        #pragma unroll
        for (int j = 0; j < 6; j++) {
            u64f2 wxy = WrF2[(eb * 6 + j) * 2];
            u64f2 wzw = WrF2[(eb * 6 + j) * 2 + 1];
            fma_f32x2(aA01, rbA2[j], wxy);
            fma_f32x2(aA23, rbA2[j], wzw);
            fma_f32x2(aB01, rbB2[j], wxy);
            fma_f32x2(aB23, rbB2[j], wzw);
        }
        float2 A01 = unpack_f32x2(aA01), A23 = unpack_f32x2(aA23);
        float2 B01 = unpack_f32x2(aB01), B23 = unpack_f32x2(aB23);
        uint4 v;
        v.x = pack_bf16(silu_f(A01.y), silu_f(A01.x));   // row g,   k c0..c0+1
        v.y = pack_bf16(silu_f(B01.y), silu_f(B01.x));   // row g+8, k c0..c0+1
        v.z = pack_bf16(silu_f(A23.y), silu_f(A23.x));   // row g,   k c0+8..c0+9
        v.w = pack_bf16(silu_f(B23.y), silu_f(B23.x));   // row g+8, k c0+8..c0+9
        HFdst[(rgA * 8 + kc) * 32 + lane] = v;
    }
}

__global__ void __launch_bounds__(256, 2) main_kernel(
    const int* __restrict__ Z, const int* __restrict__ src, const int* __restrict__ dst,
    const float* __restrict__ rbf, const float* __restrict__ dvec,
    const float* __restrict__ Wr, const float* __restrict__ brbf,
    float* __restrict__ out, int E, int nTiles)
{
    extern __shared__ unsigned sm[];
    uint4*    HF0   = (uint4*)sm;
    uint4*    HF1   = HF0 + (HF_WORDS / 4);
    float*    WrF_s = (float*)(sm + 2 * HF_WORDS);
    float*    brF_s = WrF_s + WRF_WORDS;
    unsigned* RB    = sm + 2 * HF_WORDS + WRF_WORDS + BRF_WORDS;   // 3 slots

    int tid = threadIdx.x;
    // Wr fragment pack: WrF[(kc*4+q)*6 + j] = {Wr[c0][j],Wr[c0+1][j],Wr[c0+8][j],Wr[c0+9][j]}
    for (int i = tid; i < WRF_WORDS; i += 256) {
        int entry = i >> 2, comp = i & 3;
        int kc = entry / 24, rem = entry - kc * 24;
        int qq = rem / 6, j = rem - qq * 6;
        int col = kc * 16 + 2 * qq + (comp & 1) + ((comp >> 1) * 8);
        WrF_s[i] = __ldg(Wr + col * 6 + j);
    }
    for (int i = tid; i < BRF_WORDS; i += 256) {
        int entry = i >> 2, comp = i & 3;
        int kc = entry >> 2, qq = entry & 3;
        int col = kc * 16 + 2 * qq + (comp & 1) + ((comp >> 1) * 8);
        brF_s[i] = __ldg(brbf + col);
    }

    int lane = tid & 31, w = tid >> 5;
    int g = lane >> 2, q = lane & 3;
    int rgA = w & 3, kcA = (w >> 2) * 4;  // phase A: row-group (0..3), chunk range
    int rA0 = rgA * 16 + g;
    int mq = w >> 2, h = w & 3;           // phase B: 32-row group, col pairs 2h,2h+1
    size_t envBase = (size_t)E * 128;
    const float PIf = 3.14159265358979323846f;
    const u64f2* WrF2 = (const u64f2*)WrF_s;
    const u64f2* brF2 = (const u64f2*)brF_s;
    uint32_t RB_u32 = (uint32_t)__cvta_generic_to_shared(RB);

    // W3 B-fragments: register-resident for this warp's two column pairs
    uint4 BR0[8], BR1[8];
    {
        const uint4* GW = (const uint4*)g_W3F;
        #pragma unroll
        for (int kc = 0; kc < 8; kc++) {
            BR0[kc] = __ldg(GW + (kc * 8 + 2 * h)     * 32 + lane);
            BR1[kc] = __ldg(GW + (kc * 8 + 2 * h + 1) * 32 + lane);
        }
    }

    int t = blockIdx.x;
    if (t >= nTiles) return;
    int grid = gridDim.x;

    // ---- prologue: stage T0, T1; then A(T0) into HF0 ----
    fill_slot(RB, RB_u32, t * 64, tid, E, rbf, dvec, src, dst);
    CP_COMMIT();
    if (t + grid < nTiles)
        fill_slot(RB + RB_WORDS, RB_u32 + RB_WORDS * 4, (t + grid) * 64, tid, E, rbf, dvec, src, dst);
    CP_COMMIT();
    CP_WAIT(1);          // slot 0 (T0) complete
    __syncthreads();     // all fills + WrF/brF visible

    phase_a(HF0, (const float*)RB, rA0, rgA, kcA, lane, q, WrF2, brF2);

    int p = 0, sc = 0;

    // ---- pipelined main loop: one barrier per tile ----
    while (t < nTiles) {
        CP_WAIT(0);                            // next tile's slot complete (own)
        __syncthreads();                       // HF[p] + all fills visible
        int base = t * 64;
        int tn = t + grid;
        uint4* HFr = p ? HF1 : HF0;            // B reads
        uint4* HFw = p ? HF0 : HF1;            // A writes
        unsigned* SC = RB + sc * RB_WORDS;             // current tile inputs
        int sn = sc + 1; if (sn >= 3) sn = 0;
        unsigned* SN = RB + sn * RB_WORDS;             // next tile inputs
        int sf = sc + 2; if (sf >= 3) sf -= 3;         // (sc+2) mod 3

        // stage tile t + 2*grid (2 iterations of cover)
        int tf = tn + grid;
        if (tf < nTiles)
            fill_slot(RB + sf * RB_WORDS, RB_u32 + (unsigned)sf * RB_WORDS * 4,
                      tf * 64, tid, E, rbf, dvec, src, dst);
        CP_COMMIT();

        const float* dv_s  = (const float*)SC + 384;
        const int*   src_s = (const int*)SC + 448;
        const int*   dst_s = (const int*)SC + 512;

        // epilogue z-chain (src/dst from SMEM; Z + PTS are L2-hot)
        int r0 = (2 * mq) * 16 + g;            // mt=0 base row
        int r1 = r0 + 16;                      // mt=1 base row
        int e00 = base + r0, e01 = e00 + 8;
        int e10 = base + r1, e11 = e10 + 8;
        int s00 = src_s[r0],     d00 = dst_s[r0];
        int s01 = src_s[r0 + 8], d01 = dst_s[r0 + 8];
        int s10 = src_s[r1],     d10 = dst_s[r1];
        int s11 = src_s[r1 + 8], d11 = dst_s[r1 + 8];

        // bessel / envelope branch for tile t: 192 threads, 2 sins, float2 store
        if (tid < 192) {
            int e_loc = tid / 3, c3 = tid - e_loc * 3;
            int e = base + e_loc;
            if (e < E) {
                float x = dv_s[e_loc] * 0.2f;
                float inv = 1.0f / x;
                float x2 = x*x, x4 = x2*x2, x5 = x4*x, x6 = x5*x, x7 = x6*x;
                float env = inv - 28.0f*x5 + 48.0f*x6 - 21.0f*x7;   // p = 6
                float s = env * inv;
                float2 vv;
                vv.x = s * __sinf(((float)(2 * c3 + 1) * PIf) * x);
                vv.y = s * __sinf(((float)(2 * c3 + 2) * PIf) * x);
                *(float2*)(out + envBase + (size_t)e * 6 + 2 * c3) = vv;
            }
        }

        const float* P00 = g_PTS + ((size_t)__ldg(Z + s00) * N_TYPES + __ldg(Z + d00)) * 128;
        const float* P01 = g_PTS + ((size_t)__ldg(Z + s01) * N_TYPES + __ldg(Z + d01)) * 128;
        const float* P10 = g_PTS + ((size_t)__ldg(Z + s10) * N_TYPES + __ldg(Z + d10)) * 128;
        const float* P11 = g_PTS + ((size_t)__ldg(Z + s11) * N_TYPES + __ldg(Z + d11)) * 128;

        // ---- phase A(tn) -> HFw (rbf from SMEM slot sn, packed FFMA2) ----
        if (tn < nTiles)
            phase_a(HFw, (const float*)SN, rA0, rgA, kcA, lane, q, WrF2, brF2);

        // ---- MMA loop: A via LDS.128, B from registers ----
        float c[2][4][4];
        #pragma unroll
        for (int mt = 0; mt < 2; mt++)
            #pragma unroll
            for (int nt = 0; nt < 4; nt++)
                { c[mt][nt][0]=0.f; c[mt][nt][1]=0.f; c[mt][nt][2]=0.f; c[mt][nt][3]=0.f; }

        #pragma unroll
        for (int kc = 0; kc < 8; kc++) {
            uint4 A0 = HFr[((2 * mq)     * 8 + kc) * 32 + lane];
            uint4 A1 = HFr[((2 * mq + 1) * 8 + kc) * 32 + lane];
            uint4 B0 = BR0[kc], B1 = BR1[kc];
            mma_bf16(c[0][0], A0.x, A0.y, A0.z, A0.w, B0.x, B0.y);
            mma_bf16(c[0][1], A0.x, A0.y, A0.z, A0.w, B0.z, B0.w);
            mma_bf16(c[0][2], A0.x, A0.y, A0.z, A0.w, B1.x, B1.y);
            mma_bf16(c[0][3], A0.x, A0.y, A0.z, A0.w, B1.z, B1.w);
            mma_bf16(c[1][0], A1.x, A1.y, A1.z, A1.w, B0.x, B0.y);
            mma_bf16(c[1][1], A1.x, A1.y, A1.z, A1.w, B0.z, B0.w);
            mma_bf16(c[1][2], A1.x, A1.y, A1.z, A1.w, B1.x, B1.y);
            mma_bf16(c[1][3], A1.x, A1.y, A1.z, A1.w, B1.z, B1.w);
        }

        // ---- epilogue: float4 loads/stores via pair-interleaved columns ----
        // pair pp covers logical cols (2h+pp)*16 + q*4 .. +3:
        //   {c[mt][2pp][0], c[mt][2pp][1], c[mt][2pp+1][0], c[mt][2pp+1][1]} (row g)
        //   {c[mt][2pp][2], c[mt][2pp][3], c[mt][2pp+1][2], c[mt][2pp+1][3]} (row g+8)
        #pragma unroll
        for (int mt = 0; mt < 2; mt++) {
            int e0 = mt ? e10 : e00;
            int e1 = mt ? e11 : e01;
            const float* Pa = mt ? P10 : P00;
            const float* Pb = mt ? P11 : P01;
            float* o0 = out + (size_t)e0 * 128;
            float* o1 = out + (size_t)e1 * 128;
            bool st0 = (e0 < E), st1 = (e1 < E);
            #pragma unroll
            for (int pp = 0; pp < 2; pp++) {
                int col = (2 * h + pp) * 16 + q * 4;
                int n0 = 2 * pp, n1 = 2 * pp + 1;
                float4 pa = __ldg((const float4*)(Pa + col));
                float4 pb = __ldg((const float4*)(Pb + col));
                float4 v0, v1;
                v0.x = silu_f(c[mt][n0][0] + pa.x);
                v0.y = silu_f(c[mt][n0][1] + pa.y);
                v0.z = silu_f(c[mt][n1][0] + pa.z);
                v0.w = silu_f(c[mt][n1][1] + pa.w);
                v1.x = silu_f(c[mt][n0][2] + pb.x);
                v1.y = silu_f(c[mt][n0][3] + pb.y);
                v1.z = silu_f(c[mt][n1][2] + pb.z);
                v1.w = silu_f(c[mt][n1][3] + pb.w);
                if (st0) *(float4*)(o0 + col) = v0;
                if (st1) *(float4*)(o1 + col) = v1;
            }
        }

        t = tn; p ^= 1; sc = sn;
    }
}

extern "C" void kernel_launch(void* const* d_in, const int* in_sizes, int n_in,
                              void* d_out, int out_size) {
    const int*   Z    = (const int*)d_in[0];
    const int*   src  = (const int*)d_in[1];
    const int*   dst  = (const int*)d_in[2];
    const float* rbf  = (const float*)d_in[3];
    const float* d    = (const float*)d_in[4];
    const float* emb  = (const float*)d_in[5];
    const float* Wr   = (const float*)d_in[6];
    const float* brbf = (const float*)d_in[7];
    const float* Wd   = (const float*)d_in[8];
    const float* bd   = (const float*)d_in[9];
    int E = in_sizes[1];
    int nTiles = (E + 63) / 64;

    precompute_kernel<<<N_TYPES + 32, 256>>>(emb, Wd, bd);
    ptsum_kernel<<<1184, 256>>>();

    cudaFuncSetAttribute(main_kernel, cudaFuncAttributeMaxDynamicSharedMemorySize, SMEM_BYTES);
    int dev = 0, nsm = 148;
    cudaGetDevice(&dev);
    cudaDeviceGetAttribute(&nsm, cudaDevAttrMultiProcessorCount, dev);

    main_kernel<<<2 * nsm, 256, SMEM_BYTES>>>(Z, src, dst, rbf, d, Wr, brbf,
                                              (float*)d_out, E, nTiles);
}